// round 10
// baseline (speedup 1.0000x reference)
#include <cuda_runtime.h>
#include <cuda_bf16.h>
#include <math.h>

typedef unsigned int u32;
typedef unsigned long long u64;
#define DEVFN __device__ __forceinline__

constexpr int G_MAX = 131072;
__device__ float g_res[(size_t)G_MAX * 64];

// ---------------------------------------------------------------------------
// mma.sync / ldmatrix helpers (baseline PTX, valid on plain sm_103)
// ---------------------------------------------------------------------------
DEVFN u32 smem_u32(const void* p) {
    u32 a;
    asm("{ .reg .u64 t; cvta.to.shared.u64 t, %1; cvt.u32.u64 %0, t; }" : "=r"(a) : "l"(p));
    return a;
}
DEVFN void ldsm4(u32& r0, u32& r1, u32& r2, u32& r3, u32 addr) {
    asm volatile("ldmatrix.sync.aligned.m8n8.x4.shared.b16 {%0,%1,%2,%3}, [%4];"
                 : "=r"(r0), "=r"(r1), "=r"(r2), "=r"(r3) : "r"(addr));
}
DEVFN void ldsm4t(u32& r0, u32& r1, u32& r2, u32& r3, u32 addr) {
    asm volatile("ldmatrix.sync.aligned.m8n8.x4.trans.shared.b16 {%0,%1,%2,%3}, [%4];"
                 : "=r"(r0), "=r"(r1), "=r"(r2), "=r"(r3) : "r"(addr));
}
DEVFN void mma16816(float* c, const u32* a, u32 b0, u32 b1) {
    asm volatile(
        "mma.sync.aligned.m16n8k16.row.col.f32.bf16.bf16.f32 "
        "{%0,%1,%2,%3}, {%4,%5,%6,%7}, {%8,%9}, {%0,%1,%2,%3};"
        : "+f"(c[0]), "+f"(c[1]), "+f"(c[2]), "+f"(c[3])
        : "r"(a[0]), "r"(a[1]), "r"(a[2]), "r"(a[3]), "r"(b0), "r"(b1));
}
#define SWZ(o) ((o) ^ (((o) >> 3) & 0x70))

// ---------------------------------------------------------------------------
// f32x2 packed helpers + tanh
// ---------------------------------------------------------------------------
DEVFN u64 packf2(float lo, float hi) {
    u64 r; asm("mov.b64 %0, {%1, %2};" : "=l"(r) : "f"(lo), "f"(hi)); return r;
}
DEVFN u64 pack2(float x) { return packf2(x, x); }
DEVFN float2 unpk(u64 v) {
    float lo, hi; asm("mov.b64 {%0, %1}, %2;" : "=f"(lo), "=f"(hi) : "l"(v));
    return make_float2(lo, hi);
}
DEVFN u64 ffma2(u64 a, u64 b, u64 c) {
    u64 d; asm("fma.rn.f32x2 %0, %1, %2, %3;" : "=l"(d) : "l"(a), "l"(b), "l"(c));
    return d;
}
DEVFN u64 fadd2(u64 a, u64 b) {
    u64 d; asm("add.rn.f32x2 %0, %1, %2;" : "=l"(d) : "l"(a), "l"(b)); return d;
}
DEVFN float ftanh(float x) {
    float e; asm("ex2.approx.f32 %0, %1;" : "=f"(e) : "f"(x * 2.885390081777927f));
    float r; asm("rcp.approx.f32 %0, %1;" : "=f"(r) : "f"(e + 1.0f));
    return fmaf(-2.0f, r, 1.0f);
}
DEVFN unsigned short bfu(float x) { return __bfloat16_as_ushort(__float2bfloat16(x)); }
DEVFN float bff(unsigned short u) { return __bfloat162float(__ushort_as_bfloat16(u)); }
DEVFN void split2(float a, float b, u32& hi, u32& lo) {
    unsigned short ha = bfu(a), hb = bfu(b);
    float ra = a - bff(ha), rb = b - bff(hb);
    hi = (u32)ha | ((u32)hb << 16);
    lo = (u32)bfu(ra) | ((u32)bfu(rb) << 16);
}

// ---------------------------------------------------------------------------
// Warp GEMM: D[16m x 8*2*NTP n] += (Ah+Al) @ (Wh+Wl), K=64, dropping Al*Wl.
// A tile: 128m x 64k bf16, 128B rows, SWZ.  W tile: 64k x 64n bf16, 128B rows, SWZ.
// ---------------------------------------------------------------------------
template<int NTP>
DEVFN void warp_gemm(float (&acc)[2 * NTP][4], u32 Ab, u32 Alb, u32 Wh, u32 Wl,
                     int mrow, int noff, int lane) {
    u32 ah[4][4], al[4][4];
    const u32 arow = (u32)(mrow + (lane & 15));
    const u32 acg  = (u32)((lane >> 4) * 16);
#pragma unroll
    for (int ks = 0; ks < 4; ks++) {
        u32 off = arow * 128 + (u32)ks * 32 + acg;
        ldsm4(ah[ks][0], ah[ks][1], ah[ks][2], ah[ks][3], Ab  + SWZ(off));
        ldsm4(al[ks][0], al[ks][1], al[ks][2], al[ks][3], Alb + SWZ(off));
    }
#pragma unroll
    for (int ks = 0; ks < 4; ks++) {
        u32 krow = (u32)(ks * 16 + (lane & 15));
        u32 cg   = (u32)((lane >> 4) * 16);
#pragma unroll
        for (int p = 0; p < NTP; p++) {
            u32 boff = krow * 128 + (u32)(noff + p * 16) * 2 + cg;
            u32 b0, b1, b2, b3;
            ldsm4t(b0, b1, b2, b3, Wh + SWZ(boff));
            mma16816(acc[2 * p],     ah[ks], b0, b1);
            mma16816(acc[2 * p + 1], ah[ks], b2, b3);
            mma16816(acc[2 * p],     al[ks], b0, b1);
            mma16816(acc[2 * p + 1], al[ks], b2, b3);
            u32 c0, c1, c2, c3;
            ldsm4t(c0, c1, c2, c3, Wl + SWZ(boff));
            mma16816(acc[2 * p],     ah[ks], c0, c1);
            mma16816(acc[2 * p + 1], ah[ks], c2, c3);
        }
    }
}

// Store m16n8 D frags to fp32 smem F (stride 132 floats)
template<int NT>
DEVFN void store_acc(float* F, const float (&acc)[NT][4], int mt, int colbase, int lane) {
    int r  = mt * 16 + (lane >> 2);
    int cb = colbase + (lane & 3) * 2;
#pragma unroll
    for (int nt = 0; nt < NT; nt++) {
        int c = cb + nt * 8;
        *(float2*)&F[r * 132 + c]       = make_float2(acc[nt][0], acc[nt][1]);
        *(float2*)&F[(r + 8) * 132 + c] = make_float2(acc[nt][2], acc[nt][3]);
    }
}

// ---------------------------------------------------------------------------
// Conv smem (bf16 tiles first; offsets multiples of 1024 for SWZ)
// ---------------------------------------------------------------------------
struct SmemTC {
    __nv_bfloat16 Ahi[8192], Alo[8192];          //  32768 B : A tile 128x64
    __nv_bfloat16 Wp1h[4096], Wp1l[4096];        //  16384 B
    __nv_bfloat16 Ws1h[4096], Ws1l[4096];        //  16384 B
    __nv_bfloat16 Wp2h[4096], Wp2l[4096];        //  16384 B
    float  F[128 * 132];                         //  67584 B
    float2 Wn1p[2048], Ws2p[2048], Wn2p[2048];   //  49152 B
    float  NE[1344], NT_[1344], SM1[1344];       //  16128 B
    float  bp1s[64], b1s[64], bp2s[64], b2s[64]; //   1024 B
};                                               // 215808 B total

DEVFN void stage_w_split(__nv_bfloat16* Wh, __nv_bfloat16* Wl,
                         const float* __restrict__ W, int tid) {
    char* h = (char*)Wh; char* l = (char*)Wl;
    for (int i = tid; i < 64 * 32; i += 512) {
        int k = i >> 5, seg = i & 31;                 // seg = pair of n
        u32 hi, lo; split2(W[k * 64 + 2 * seg], W[k * 64 + 2 * seg + 1], hi, lo);
        u32 off = SWZ((u32)(k * 128 + seg * 4));
        *(u32*)(h + off) = hi; *(u32*)(l + off) = lo;
    }
}

__global__ void __launch_bounds__(512, 1)
conv_tc(const float* __restrict__ obs,
        const float* __restrict__ Wp1, const float* __restrict__ bp1,
        const float* __restrict__ Ws1, const float* __restrict__ Wn1,
        const float* __restrict__ b1,
        const float* __restrict__ Wp2, const float* __restrict__ bp2,
        const float* __restrict__ Ws2, const float* __restrict__ Wn2,
        const float* __restrict__ b2,
        int G)
{
    extern __shared__ __align__(1024) char sraw[];
    SmemTC* S = (SmemTC*)sraw;
    const int tid  = threadIdx.x;
    const int wid  = tid >> 5;
    const int lane = tid & 31;

    // ---- stage weights (once) ----
    stage_w_split(S->Wp1h, S->Wp1l, Wp1, tid);
    stage_w_split(S->Ws1h, S->Ws1l, Ws1, tid);
    stage_w_split(S->Wp2h, S->Wp2l, Wp2, tid);
    for (int h = tid; h < 2048; h += 512) {
        int j = h >> 5, cp = h & 31;
        S->Wn1p[h] = make_float2(Wn1[j * 64 + cp], Wn1[j * 64 + cp + 32]);
        S->Ws2p[h] = make_float2(Ws2[j * 64 + cp], Ws2[j * 64 + cp + 32]);
        S->Wn2p[h] = make_float2(Wn2[j * 64 + cp], Wn2[j * 64 + cp + 32]);
    }
    if (tid < 64) {
        S->bp1s[tid] = bp1[tid]; S->b1s[tid] = b1[tid];
        S->bp2s[tid] = bp2[tid]; S->b2s[tid] = b2[tid];
    }
    __syncthreads();

    char* Ah = (char*)S->Ahi; char* Al = (char*)S->Alo;
    const u32 Ab  = smem_u32(S->Ahi), Alb = smem_u32(S->Alo);
    const u32 P1h = smem_u32(S->Wp1h), P1l = smem_u32(S->Wp1l);
    const u32 S1h = smem_u32(S->Ws1h), S1l = smem_u32(S->Ws1l);
    const u32 P2h = smem_u32(S->Wp2h), P2l = smem_u32(S->Wp2l);
    float* F = S->F;

    const size_t maxrow = (size_t)G * 6 - 1;
    const int ntiles = (G + 20) / 21;
    const int mt = wid & 7;          // m-tile (16 rows)
    const int nh = wid >> 3;         // n-half

    for (int tile = blockIdx.x; tile < ntiles; tile += gridDim.x) {
        const int gb = tile * 21;
        const size_t rowbase = (size_t)gb * 6;

        // ---- stage obs tile -> Ahi/Alo (bf16 split, SWZ) ----
        for (int h = tid; h < 128 * 16; h += 512) {     // (m, seg of 4 floats)
            int m = h >> 4, seg = h & 15;
            size_t gr = rowbase + m; if (gr > maxrow) gr = maxrow;
            float4 v = *(const float4*)(obs + gr * 64 + seg * 4);
            u32 h0, l0, h1v, l1;
            split2(v.x, v.y, h0, l0);
            split2(v.z, v.w, h1v, l1);
            u32 o0 = SWZ((u32)(m * 128 + seg * 8));
            u32 o1 = SWZ((u32)(m * 128 + seg * 8 + 4));
            *(u32*)(Ah + o0) = h0;  *(u32*)(Al + o0) = l0;
            *(u32*)(Ah + o1) = h1v; *(u32*)(Al + o1) = l1;
        }
        __syncthreads();

        // ---- MMA1: F[.,0:64] = obs@Wp1 (half 0), F[.,64:128] = obs@Ws1 (half 1) ----
        {
            float acc[8][4];
#pragma unroll
            for (int i = 0; i < 8; i++)
#pragma unroll
                for (int k = 0; k < 4; k++) acc[i][k] = 0.f;
            warp_gemm<4>(acc, Ab, Alb, nh ? S1h : P1h, nh ? S1l : P1l,
                         mt * 16, 0, lane);
            store_acc<8>(F, acc, mt, nh * 64, lane);
        }
        __syncthreads();

        // ---- epA: neigh[g][j] = relu(max6 P + bp1) ----
        for (int h = tid; h < 1344; h += 512) {
            int g = h >> 6, j = h & 63;
            float mx = -1e30f;
#pragma unroll
            for (int i = 0; i < 6; i++) mx = fmaxf(mx, F[(6 * g + i) * 132 + j]);
            S->NE[h] = fmaxf(mx + S->bp1s[j], 0.f);
        }
        __syncthreads();

        // ---- epB: nt[g][c] = neigh@Wn1 + b1 (paired FFMA2) ----
        for (int h = tid; h < 672; h += 512) {
            int g = h >> 5, cp = h & 31;
            u64 acc = packf2(S->b1s[cp], S->b1s[cp + 32]);
#pragma unroll 8
            for (int j = 0; j < 64; j++)
                acc = ffma2(pack2(S->NE[g * 64 + j]), *(u64*)&S->Wn1p[j * 32 + cp], acc);
            float2 v = unpk(acc);
            S->NT_[g * 64 + cp] = v.x; S->NT_[g * 64 + cp + 32] = v.y;
        }
        __syncthreads();

        // ---- epC: h1 = tanh(S + nt) -> F[.,0:64] fp32 AND Ahi/Alo (split) ----
        {
            int m = tid >> 2, jb = (tid & 3) * 16;
            int g = m / 6; if (g > 20) g = 20;
#pragma unroll
            for (int i = 0; i < 8; i++) {
                int j0 = jb + 2 * i;
                float v0 = ftanh(F[m * 132 + 64 + j0]     + S->NT_[g * 64 + j0]);
                float v1 = ftanh(F[m * 132 + 64 + j0 + 1] + S->NT_[g * 64 + j0 + 1]);
                F[m * 132 + j0] = v0; F[m * 132 + j0 + 1] = v1;
                u32 hi, lo; split2(v0, v1, hi, lo);
                u32 off = SWZ((u32)(m * 128 + j0 * 2));
                *(u32*)(Ah + off) = hi; *(u32*)(Al + off) = lo;
            }
        }
        __syncthreads();

        // ---- epD: s1[g][j] = sum6 h1 ----
        for (int h = tid; h < 1344; h += 512) {
            int g = h >> 6, j = h & 63;
            float s = 0.f;
#pragma unroll
            for (int i = 0; i < 6; i++) s += F[(6 * g + i) * 132 + j];
            S->SM1[h] = s;
        }

        // ---- MMA2: F[.,64:128] = h1 @ Wp2 (each warp 32 cols) ----
        {
            float acc[4][4];
#pragma unroll
            for (int i = 0; i < 4; i++)
#pragma unroll
                for (int k = 0; k < 4; k++) acc[i][k] = 0.f;
            warp_gemm<2>(acc, Ab, Alb, P2h, P2l, mt * 16, nh * 32, lane);
            store_acc<4>(F, acc, mt, 64 + nh * 32, lane);
        }
        __syncthreads();

        // ---- epE: neigh2[g][c] = relu(max6 P2 + bp2) ----
        for (int h = tid; h < 1344; h += 512) {
            int g = h >> 6, c = h & 63;
            float mx = -1e30f;
#pragma unroll
            for (int i = 0; i < 6; i++) mx = fmaxf(mx, F[(6 * g + i) * 132 + 64 + c]);
            S->NE[h] = fmaxf(mx + S->bp2s[c], 0.f);
        }
        __syncthreads();

        // ---- epF: res = b2 + neigh2@Wn2 + (s1@Ws2)/6 -> g_res ----
        for (int h = tid; h < 672; h += 512) {
            int g = h >> 5, cp = h & 31;
            u64 a1 = packf2(S->b2s[cp], S->b2s[cp + 32]);
            u64 a2 = 0ull;
#pragma unroll 8
            for (int j = 0; j < 64; j++) {
                a1 = ffma2(pack2(S->NE[g * 64 + j]),  *(u64*)&S->Wn2p[j * 32 + cp], a1);
                a2 = ffma2(pack2(S->SM1[g * 64 + j]), *(u64*)&S->Ws2p[j * 32 + cp], a2);
            }
            float2 v1 = unpk(a1), v2 = unpk(a2);
            int gg = gb + g;
            if (gg < G) {
                g_res[(size_t)gg * 64 + cp]      = fmaf(v2.x, 1.0f / 6.0f, v1.x);
                g_res[(size_t)gg * 64 + cp + 32] = fmaf(v2.y, 1.0f / 6.0f, v1.y);
            }
        }
        __syncthreads();
    }
}

// ---------------------------------------------------------------------------
// MLP kernel (unchanged known-good scalar version, ~168us)
// ---------------------------------------------------------------------------
DEVFN void stage_quads(float4* dst, const float* __restrict__ src, int tid, int nt) {
    for (int idx = tid; idx < 1024; idx += nt) {
        int k2 = idx >> 5, j = idx & 31;
        const float* r0 = src + (2 * k2) * 64;
        const float* r1 = src + (2 * k2 + 1) * 64;
        dst[idx] = make_float4(r0[j], r0[j + 32], r1[j], r1[j + 32]);
    }
}

template<int NP>
DEVFN void pass_gemm(u64 (&acc)[NP][2], const float4* __restrict__ P,
                     const float4* __restrict__ W, int j) {
    const ulonglong2* __restrict__ P2 = reinterpret_cast<const ulonglong2*>(P);
#pragma unroll 4
    for (int k2 = 0; k2 < 32; k2++) {
        float4 w = W[k2 * 32 + j];
        u64 A0 = pack2(w.x), A1 = pack2(w.y), B0 = pack2(w.z), B1 = pack2(w.w);
#pragma unroll
        for (int p = 0; p < NP; p++) {
            ulonglong2 X = P2[p * 32 + k2];
            acc[p][0] = ffma2(X.x, A0, acc[p][0]);
            acc[p][1] = ffma2(X.x, A1, acc[p][1]);
            acc[p][0] = ffma2(X.y, B0, acc[p][0]);
            acc[p][1] = ffma2(X.y, B1, acc[p][1]);
        }
    }
}

struct SmemMlp {
    float4 W[6][1024];
    float4 rsp[16][6 * 32];
    float4 bufA[16][6 * 32];
    float  W4[2][128];
    float  B1[128], B2[128], B3[128], B4[4];
};

__global__ void __launch_bounds__(512, 1)
mlp_kernel(const float* __restrict__ MW1, const float* __restrict__ Mb1,
           const float* __restrict__ MW2, const float* __restrict__ Mb2,
           const float* __restrict__ MW3, const float* __restrict__ Mb3,
           const float* __restrict__ MW4, const float* __restrict__ Mb4,
           float* __restrict__ out, int G)
{
    extern __shared__ __align__(1024) char sraw[];
    SmemMlp* S = (SmemMlp*)sraw;
    const int tid = threadIdx.x;

    stage_quads(S->W[0], MW1,        tid, 512);
    stage_quads(S->W[1], MW1 + 4096, tid, 512);
    stage_quads(S->W[2], MW2,        tid, 512);
    stage_quads(S->W[3], MW2 + 4096, tid, 512);
    stage_quads(S->W[4], MW3,        tid, 512);
    stage_quads(S->W[5], MW3 + 4096, tid, 512);
    if (tid < 256) ((float*)S->W4)[tid] = MW4[tid];
    if (tid < 128) { S->B1[tid] = Mb1[tid]; S->B2[tid] = Mb2[tid]; S->B3[tid] = Mb3[tid]; }
    if (tid < 4)   S->B4[tid] = Mb4[tid];
    __syncthreads();

    const int wid = tid >> 5, j = tid & 31;
    float4* rsp = S->rsp[wid];
    float4* bAp = S->bufA[wid];
    float*  rsf = (float*)rsp;
    float*  bAf = (float*)bAp;
    const float2* r2 = (const float2*)g_res;

    const int NB = (G + 11) / 12;
    const int lastg = G - 1;

    for (int b = blockIdx.x * 16 + wid; b < NB; b += gridDim.x * 16) {
        const int gb = b * 12;

#pragma unroll
        for (int t = 0; t < 2; t++) {
#pragma unroll
            for (int i = 0; i < 6; i++) {
                int ga = gb + 2 * i; if (ga > lastg) ga = lastg;
                int gc = ga + 1;     if (gc > lastg) gc = lastg;
                float2 a = r2[(size_t)ga * 32 + j];
                float2 c = r2[(size_t)gc * 32 + j];
                rsp[i * 32 + j] = make_float4(a.x, c.x, a.y, c.y);
            }
            __syncwarp();

            u64 acc[6][2];
            {
                u64 d0 = pack2(S->B1[t * 64 + j]), d1 = pack2(S->B1[t * 64 + j + 32]);
#pragma unroll
                for (int p = 0; p < 6; p++) { acc[p][0] = d0; acc[p][1] = d1; }
            }
            pass_gemm<6>(acc, rsp, S->W[t], j);
#pragma unroll
            for (int p = 0; p < 6; p++) {
                float2 c0 = unpk(acc[p][0]);
                *(u64*)&bAf[(p * 32 + (j >> 1)) * 4 + 2 * (j & 1)] =
                    packf2(fmaxf(c0.x, 0.f), fmaxf(c0.y, 0.f));
                float2 c1 = unpk(acc[p][1]);
                *(u64*)&bAf[(p * 32 + 16 + (j >> 1)) * 4 + 2 * (j & 1)] =
                    packf2(fmaxf(c1.x, 0.f), fmaxf(c1.y, 0.f));
            }
            __syncwarp();

            {
                u64 d0 = pack2(S->B2[t * 64 + j]), d1 = pack2(S->B2[t * 64 + j + 32]);
#pragma unroll
                for (int p = 0; p < 6; p++) { acc[p][0] = d0; acc[p][1] = d1; }
            }
            pass_gemm<6>(acc, bAp, S->W[2 + t], j);
#pragma unroll
            for (int p = 0; p < 6; p++) {
                float2 c0 = unpk(acc[p][0]);
                *(u64*)&rsf[(p * 32 + (j >> 1)) * 4 + 2 * (j & 1)] =
                    packf2(fmaxf(c0.x, 0.f), fmaxf(c0.y, 0.f));
                float2 c1 = unpk(acc[p][1]);
                *(u64*)&rsf[(p * 32 + 16 + (j >> 1)) * 4 + 2 * (j & 1)] =
                    packf2(fmaxf(c1.x, 0.f), fmaxf(c1.y, 0.f));
            }
            __syncwarp();

            {
                u64 d0 = pack2(S->B3[t * 64 + j]), d1 = pack2(S->B3[t * 64 + j + 32]);
#pragma unroll
                for (int p = 0; p < 6; p++) { acc[p][0] = d0; acc[p][1] = d1; }
            }
            pass_gemm<6>(acc, rsp, S->W[4 + t], j);
            float xj[12], xj32[12];
#pragma unroll
            for (int p = 0; p < 6; p++) {
                float2 c0 = unpk(acc[p][0]);
                xj[2 * p] = fmaxf(c0.x, 0.f);  xj[2 * p + 1] = fmaxf(c0.y, 0.f);
                float2 c1 = unpk(acc[p][1]);
                xj32[2 * p] = fmaxf(c1.x, 0.f); xj32[2 * p + 1] = fmaxf(c1.y, 0.f);
            }

            float2 m0 = *(const float2*)&S->W4[t][j * 2];
            float2 m1 = *(const float2*)&S->W4[t][(j + 32) * 2];
            const float bo0 = S->B4[t * 2], bo1 = S->B4[t * 2 + 1];
#pragma unroll
            for (int g = 0; g < 12; g++) {
                float p0 = xj[g] * m0.x + xj32[g] * m1.x;
                float p1 = xj[g] * m0.y + xj32[g] * m1.y;
                u64 pk = packf2(p0, p1);
#pragma unroll
                for (int off = 16; off; off >>= 1)
                    pk = fadd2(pk, __shfl_xor_sync(0xffffffffu, pk, off));
                float2 o = unpk(pk);
                const bool valid = (gb + g) < G;
                if (t == 0) {
                    if (j < 5 && valid) {
                        float o0 = tanhf(o.x + bo0), o1 = tanhf(o.y + bo1);
                        *(float2*)&out[(size_t)(gb + g) * 12 + j * 2] = make_float2(o0, o1);
                    }
                } else {
                    if (j == 0 && valid) {
                        float o0 = tanhf(o.x + bo0), o1 = tanhf(o.y + bo1);
                        *(float2*)&out[(size_t)(gb + g) * 12 + 10] = make_float2(o0, o1);
                    }
                }
            }
            __syncwarp();
        }
    }
}

// ---------------------------------------------------------------------------
extern "C" void kernel_launch(void* const* d_in, const int* in_sizes, int n_in,
                              void* d_out, int out_size) {
    const float* obs = (const float*)d_in[0];
    const float* Wp1 = (const float*)d_in[1];
    const float* bp1 = (const float*)d_in[2];
    const float* Ws1 = (const float*)d_in[3];
    const float* Wn1 = (const float*)d_in[4];
    const float* b1  = (const float*)d_in[5];
    const float* Wp2 = (const float*)d_in[6];
    const float* bp2 = (const float*)d_in[7];
    const float* Ws2 = (const float*)d_in[8];
    const float* Wn2 = (const float*)d_in[9];
    const float* b2  = (const float*)d_in[10];
    const float* MW1 = (const float*)d_in[11];
    const float* Mb1 = (const float*)d_in[12];
    const float* MW2 = (const float*)d_in[13];
    const float* Mb2 = (const float*)d_in[14];
    const float* MW3 = (const float*)d_in[15];
    const float* Mb3 = (const float*)d_in[16];
    const float* MW4 = (const float*)d_in[17];
    const float* Mb4 = (const float*)d_in[18];
    float* out = (float*)d_out;

    const int G = in_sizes[0] / 384;

    cudaFuncSetAttribute(conv_tc, cudaFuncAttributeMaxDynamicSharedMemorySize,
                         (int)sizeof(SmemTC));
    cudaFuncSetAttribute(mlp_kernel, cudaFuncAttributeMaxDynamicSharedMemorySize,
                         (int)sizeof(SmemMlp));

    conv_tc<<<148, 512, sizeof(SmemTC)>>>(obs, Wp1, bp1, Ws1, Wn1, b1,
                                          Wp2, bp2, Ws2, Wn2, b2, G);
    mlp_kernel<<<148, 512, sizeof(SmemMlp)>>>(MW1, Mb1, MW2, Mb2, MW3, Mb3,
                                              MW4, Mb4, out, G);
}